// round 3
// baseline (speedup 1.0000x reference)
#include <cuda_runtime.h>
#include <cuda_bf16.h>
#include <cstdint>

// Problem constants
#define BB 4
#define SS 1024
#define DD 1024
#define HH 16
#define HD 64
#define MROWS (BB*SS)          // 4096
#define QSCALE 0.03125f        // 1024^-0.5

typedef unsigned long long u64;

// Scratch
__device__ float g_qkv[(size_t)MROWS * 3 * DD];              // [4096, 3072]
__device__ float g_p[(size_t)BB * HH * SS * SS];             // [b,h,q,k]
__device__ float g_ao[(size_t)MROWS * DD];                   // [4096, 1024]

// ---------------------------------------------------------------------------
// f32x2 packed-FMA helpers (Blackwell)
// ---------------------------------------------------------------------------
__device__ __forceinline__ void fma2(u64& d, u64 a, u64 b) {
    asm("fma.rn.f32x2 %0, %1, %2, %0;" : "+l"(d) : "l"(a), "l"(b));
}
__device__ __forceinline__ u64 pack2(float x, float y) {
    u64 r; asm("mov.b64 %0, {%1, %2};" : "=l"(r) : "f"(x), "f"(y)); return r;
}
__device__ __forceinline__ u64 dup2(float x) { return pack2(x, x); }
__device__ __forceinline__ float2 unpk(u64 v) {
    float2 r; asm("mov.b64 {%0, %1}, %2;" : "=f"(r.x), "=f"(r.y) : "l"(v)); return r;
}

// ---------------------------------------------------------------------------
// MMA helpers
// ---------------------------------------------------------------------------
__device__ __forceinline__ void mma16816(float* d, const uint32_t* a, const uint32_t* b) {
    asm volatile(
        "mma.sync.aligned.m16n8k16.row.col.f32.bf16.bf16.f32 "
        "{%0,%1,%2,%3}, {%4,%5,%6,%7}, {%8,%9}, {%0,%1,%2,%3};"
        : "+f"(d[0]), "+f"(d[1]), "+f"(d[2]), "+f"(d[3])
        : "r"(a[0]), "r"(a[1]), "r"(a[2]), "r"(a[3]), "r"(b[0]), "r"(b[1]));
}
__device__ __forceinline__ void ldsm_x4(uint32_t* r, uint32_t addr) {
    asm volatile("ldmatrix.sync.aligned.m8n8.x4.shared.b16 {%0,%1,%2,%3}, [%4];"
                 : "=r"(r[0]), "=r"(r[1]), "=r"(r[2]), "=r"(r[3]) : "r"(addr));
}
__device__ __forceinline__ void ldsm_x2t(uint32_t* r, uint32_t addr) {
    asm volatile("ldmatrix.sync.aligned.m8n8.x2.trans.shared.b16 {%0,%1}, [%2];"
                 : "=r"(r[0]), "=r"(r[1]) : "r"(addr));
}
__device__ __forceinline__ void split_bf16(float v, __nv_bfloat16& h, __nv_bfloat16& l) {
    h = __float2bfloat16(v);
    l = __float2bfloat16(v - __bfloat162float(h));
}

// ---------------------------------------------------------------------------
// Tensor-core GEMM (split-bf16, 3 MMA passes -> ~fp32 accuracy)
// C[M,N] = A[M,K] @ B[K,N] + bias; cols < scale_cols get *scale.
// BM=BN=128, BK=32, 256 threads = 8 warps (4m x 2n), warp tile 32x64.
// ---------------------------------------------------------------------------
#define ASTRIDE 40    // bf16 elems per A smem row (32 + 8 pad): conflict-free ldsm
#define BSTRIDE 136   // bf16 elems per B smem row (128 + 8 pad)

__global__ __launch_bounds__(256) void mma_gemm_bias(
    const float* __restrict__ A, const float* __restrict__ B,
    const float* __restrict__ bias, float* __restrict__ C,
    int M, int N, int K, int scale_cols, float scale)
{
    __shared__ __nv_bfloat16 Ah[128 * ASTRIDE];
    __shared__ __nv_bfloat16 Al[128 * ASTRIDE];
    __shared__ __nv_bfloat16 Bh[32 * BSTRIDE];
    __shared__ __nv_bfloat16 Bl[32 * BSTRIDE];

    int bx = blockIdx.x, by = blockIdx.y;
    int tid  = threadIdx.x;
    int lane = tid & 31;
    int wid  = tid >> 5;
    int wm = (wid & 3) * 32;     // warp m offset in tile
    int wn = (wid >> 2) * 64;    // warp n offset in tile

    float acc[2][8][4];
    #pragma unroll
    for (int i = 0; i < 2; i++)
        #pragma unroll
        for (int j = 0; j < 8; j++)
            #pragma unroll
            for (int c = 0; c < 4; c++) acc[i][j][c] = 0.f;

    // ldmatrix source addresses (lane-dependent parts)
    uint32_t ah_base = (uint32_t)__cvta_generic_to_shared(Ah);
    uint32_t al_base = (uint32_t)__cvta_generic_to_shared(Al);
    uint32_t bh_base = (uint32_t)__cvta_generic_to_shared(Bh);
    uint32_t bl_base = (uint32_t)__cvta_generic_to_shared(Bl);
    int a_row = wm + (lane & 15);            // + mi*16
    int a_col = (lane >> 4) * 8;             // + ks*16
    int b_row = (lane & 15);                 // + ks*16
    // byte offsets
    uint32_t a_off = (uint32_t)(a_row * ASTRIDE + a_col) * 2;
    uint32_t b_off = (uint32_t)(b_row * BSTRIDE + wn) * 2;

    for (int kt = 0; kt < K; kt += 32) {
        // ---- load + split A tile: 128 x 32 ----
        #pragma unroll
        for (int it = 0; it < 4; it++) {
            int idx = tid + it * 256;
            int row = idx >> 3, c4 = idx & 7;
            float4 v = *(const float4*)&A[(size_t)(by * 128 + row) * K + kt + c4 * 4];
            __nv_bfloat16 h0, l0, h1, l1, h2, l2, h3, l3;
            split_bf16(v.x, h0, l0); split_bf16(v.y, h1, l1);
            split_bf16(v.z, h2, l2); split_bf16(v.w, h3, l3);
            __nv_bfloat162* ph = (__nv_bfloat162*)&Ah[row * ASTRIDE + c4 * 4];
            __nv_bfloat162* pl = (__nv_bfloat162*)&Al[row * ASTRIDE + c4 * 4];
            ph[0] = __nv_bfloat162(h0, h1); ph[1] = __nv_bfloat162(h2, h3);
            pl[0] = __nv_bfloat162(l0, l1); pl[1] = __nv_bfloat162(l2, l3);
        }
        // ---- load + split B tile: 32 x 128 ----
        #pragma unroll
        for (int it = 0; it < 4; it++) {
            int idx = tid + it * 256;
            int row = idx >> 5, c4 = idx & 31;
            float4 v = *(const float4*)&B[(size_t)(kt + row) * N + bx * 128 + c4 * 4];
            __nv_bfloat16 h0, l0, h1, l1, h2, l2, h3, l3;
            split_bf16(v.x, h0, l0); split_bf16(v.y, h1, l1);
            split_bf16(v.z, h2, l2); split_bf16(v.w, h3, l3);
            __nv_bfloat162* ph = (__nv_bfloat162*)&Bh[row * BSTRIDE + c4 * 4];
            __nv_bfloat162* pl = (__nv_bfloat162*)&Bl[row * BSTRIDE + c4 * 4];
            ph[0] = __nv_bfloat162(h0, h1); ph[1] = __nv_bfloat162(h2, h3);
            pl[0] = __nv_bfloat162(l0, l1); pl[1] = __nv_bfloat162(l2, l3);
        }
        __syncthreads();

        #pragma unroll
        for (int ks = 0; ks < 2; ks++) {
            uint32_t ahf[2][4], alf[2][4];
            #pragma unroll
            for (int mi = 0; mi < 2; mi++) {
                uint32_t off = a_off + (uint32_t)(mi * 16 * ASTRIDE + ks * 16) * 2;
                ldsm_x4(ahf[mi], ah_base + off);
                ldsm_x4(alf[mi], al_base + off);
            }
            #pragma unroll
            for (int ni = 0; ni < 8; ni++) {
                uint32_t off = b_off + (uint32_t)(ks * 16 * BSTRIDE + ni * 8) * 2;
                uint32_t bhf[2], blf[2];
                ldsm_x2t(bhf, bh_base + off);
                ldsm_x2t(blf, bl_base + off);
                #pragma unroll
                for (int mi = 0; mi < 2; mi++) {
                    mma16816(acc[mi][ni], ahf[mi], bhf);
                    mma16816(acc[mi][ni], ahf[mi], blf);
                    mma16816(acc[mi][ni], alf[mi], bhf);
                }
            }
        }
        __syncthreads();
    }

    // epilogue
    int group = lane >> 2, tig = lane & 3;
    bool sc = (bx * 128 < scale_cols);   // uniform per block
    #pragma unroll
    for (int mi = 0; mi < 2; mi++) {
        int row0 = by * 128 + wm + mi * 16 + group;
        #pragma unroll
        for (int ni = 0; ni < 8; ni++) {
            int col = bx * 128 + wn + ni * 8 + tig * 2;
            float b0 = bias[col], b1 = bias[col + 1];
            float2 lo = make_float2(acc[mi][ni][0] + b0, acc[mi][ni][1] + b1);
            float2 hi = make_float2(acc[mi][ni][2] + b0, acc[mi][ni][3] + b1);
            if (sc) { lo.x *= scale; lo.y *= scale; hi.x *= scale; hi.y *= scale; }
            *(float2*)&C[(size_t)row0 * N + col]       = lo;
            *(float2*)&C[(size_t)(row0 + 8) * N + col] = hi;
        }
    }
}

// ---------------------------------------------------------------------------
// Fused scores + softmax per (b, h, 32-q tile). f32x2 inner product.
// ---------------------------------------------------------------------------
#define QT 32
#define KT2 256
#define SC_SMEM ((QT*SS + 64*36 + 64*KT2) * sizeof(float))

__global__ __launch_bounds__(256) void attn_scores_softmax(
    const float* __restrict__ qkv, float* __restrict__ P)
{
    extern __shared__ float sm[];
    float* Ssc = sm;                       // [QT][1024]
    float* Qs  = Ssc + QT * SS;            // [64][36] d-major
    float* Ks  = Qs + 64 * 36;             // [64][256] d-major, swizzled

    int b  = blockIdx.z;
    int h  = blockIdx.y;
    int q0 = blockIdx.x * QT;
    int tid = threadIdx.x;
    int lane = tid & 31;
    int wq   = tid >> 5;

    for (int i = tid; i < QT * 64; i += 256) {
        int q = i >> 6, d = i & 63;
        Qs[d * 36 + q] = qkv[(size_t)(b * SS + q0 + q) * (3 * DD) + h * HD + d];
    }

    for (int kt = 0; kt < SS; kt += KT2) {
        __syncthreads();
        #pragma unroll
        for (int it = 0; it < 16; it++) {
            int i = tid + it * 256;
            int k = i >> 4, d4 = i & 15;
            float4 v = *(const float4*)&qkv[(size_t)(b * SS + kt + k) * (3 * DD) + DD + h * HD + d4 * 4];
            int sw = (d4 & 7) << 2;
            Ks[(d4 * 4 + 0) * KT2 + (k ^ sw)] = v.x;
            Ks[(d4 * 4 + 1) * KT2 + (k ^ sw)] = v.y;
            Ks[(d4 * 4 + 2) * KT2 + (k ^ sw)] = v.z;
            Ks[(d4 * 4 + 3) * KT2 + (k ^ sw)] = v.w;
        }
        __syncthreads();

        u64 acc[2][8];
        #pragma unroll
        for (int i = 0; i < 2; i++)
            #pragma unroll
            for (int j = 0; j < 8; j++) acc[i][j] = 0ull;

        #pragma unroll 4
        for (int d = 0; d < 64; d++) {
            ulonglong2 a = *(const ulonglong2*)&Qs[d * 36 + wq * 4];
            int sw = ((d >> 2) & 7) << 2;
            int kb = (lane * 4) ^ sw;
            float4 b0 = *(const float4*)&Ks[d * KT2 + kb];
            float4 b1 = *(const float4*)&Ks[d * KT2 + 128 + kb];
            u64 bd[8] = {dup2(b0.x), dup2(b0.y), dup2(b0.z), dup2(b0.w),
                         dup2(b1.x), dup2(b1.y), dup2(b1.z), dup2(b1.w)};
            #pragma unroll
            for (int j = 0; j < 8; j++) {
                fma2(acc[0][j], a.x, bd[j]);
                fma2(acc[1][j], a.y, bd[j]);
            }
        }

        #pragma unroll
        for (int rp = 0; rp < 2; rp++) {
            float2 c0 = unpk(acc[rp][0]), c1 = unpk(acc[rp][1]);
            float2 c2 = unpk(acc[rp][2]), c3 = unpk(acc[rp][3]);
            float2 c4 = unpk(acc[rp][4]), c5 = unpk(acc[rp][5]);
            float2 c6 = unpk(acc[rp][6]), c7 = unpk(acc[rp][7]);
            int rlo = wq * 4 + rp * 2, rhi = rlo + 1;
            *(float4*)&Ssc[rlo * SS + kt + lane * 4]       = make_float4(c0.x, c1.x, c2.x, c3.x);
            *(float4*)&Ssc[rlo * SS + kt + 128 + lane * 4] = make_float4(c4.x, c5.x, c6.x, c7.x);
            *(float4*)&Ssc[rhi * SS + kt + lane * 4]       = make_float4(c0.y, c1.y, c2.y, c3.y);
            *(float4*)&Ssc[rhi * SS + kt + 128 + lane * 4] = make_float4(c4.y, c5.y, c6.y, c7.y);
        }
    }
    __syncthreads();

    for (int r = wq * 4; r < wq * 4 + 4; r++) {
        const float* row = Ssc + r * SS;
        float v[32];
        float m = -1e30f;
        #pragma unroll
        for (int i = 0; i < 32; i++) {
            v[i] = row[lane + i * 32];
            m = fmaxf(m, v[i]);
        }
        #pragma unroll
        for (int o = 16; o; o >>= 1) m = fmaxf(m, __shfl_xor_sync(0xffffffffu, m, o));
        float s = 0.f;
        #pragma unroll
        for (int i = 0; i < 32; i++) { v[i] = __expf(v[i] - m); s += v[i]; }
        #pragma unroll
        for (int o = 16; o; o >>= 1) s += __shfl_xor_sync(0xffffffffu, s, o);
        float inv = 1.f / s;
        size_t base = ((size_t)(b * HH + h) * SS + q0 + r) * SS;
        #pragma unroll
        for (int i = 0; i < 32; i++) P[base + lane + i * 32] = v[i] * inv;
    }
}

// ---------------------------------------------------------------------------
// PV GEMM: AO[b,q,h,d] = sum_k P[b,h,q,k] * V[b,k,h,d]
// ---------------------------------------------------------------------------
__global__ __launch_bounds__(256) void attn_pv(
    const float* __restrict__ P, const float* __restrict__ qkv,
    float* __restrict__ AO)
{
    __shared__ float Ps[64 * 132];
    __shared__ float Vs[64 * 68];

    int b  = blockIdx.z;
    int h  = blockIdx.y;
    int q0 = blockIdx.x * 128;
    int tid = threadIdx.x;
    int tx = tid & 15;
    int ty = tid >> 4;

    u64 acc[4][4];
    #pragma unroll
    for (int i = 0; i < 4; i++)
        #pragma unroll
        for (int j = 0; j < 4; j++) acc[i][j] = 0ull;

    for (int kt = 0; kt < SS; kt += 64) {
        __syncthreads();
        #pragma unroll
        for (int it = 0; it < 8; it++) {
            int i = tid + it * 256;
            int q = i >> 4, k4 = i & 15;
            float4 pv = *(const float4*)&P[((size_t)(b * HH + h) * SS + q0 + q) * SS + kt + k4 * 4];
            Ps[(k4 * 4 + 0) * 132 + q] = pv.x;
            Ps[(k4 * 4 + 1) * 132 + q] = pv.y;
            Ps[(k4 * 4 + 2) * 132 + q] = pv.z;
            Ps[(k4 * 4 + 3) * 132 + q] = pv.w;
        }
        #pragma unroll
        for (int it = 0; it < 4; it++) {
            int i = tid + it * 256;
            int k = i >> 4, d4 = i & 15;
            *(float4*)&Vs[k * 68 + d4 * 4] =
                *(const float4*)&qkv[(size_t)(b * SS + kt + k) * (3 * DD) + 2 * DD + h * HD + d4 * 4];
        }
        __syncthreads();

        #pragma unroll 4
        for (int k = 0; k < 64; k++) {
            ulonglong2 p0 = *(const ulonglong2*)&Ps[k * 132 + ty * 8];
            ulonglong2 p1 = *(const ulonglong2*)&Ps[k * 132 + ty * 8 + 4];
            u64 am[4] = {p0.x, p0.y, p1.x, p1.y};
            float4 v = *(const float4*)&Vs[k * 68 + tx * 4];
            u64 vd[4] = {dup2(v.x), dup2(v.y), dup2(v.z), dup2(v.w)};
            #pragma unroll
            for (int i = 0; i < 4; i++)
                #pragma unroll
                for (int j = 0; j < 4; j++)
                    fma2(acc[i][j], am[i], vd[j]);
        }
    }

    #pragma unroll
    for (int qp = 0; qp < 4; qp++) {
        float2 c0 = unpk(acc[qp][0]), c1 = unpk(acc[qp][1]);
        float2 c2 = unpk(acc[qp][2]), c3 = unpk(acc[qp][3]);
        int qlo = q0 + ty * 8 + qp * 2;
        *(float4*)&AO[(size_t)(b * SS + qlo) * DD + h * HD + tx * 4] =
            make_float4(c0.x, c1.x, c2.x, c3.x);
        *(float4*)&AO[(size_t)(b * SS + qlo + 1) * DD + h * HD + tx * 4] =
            make_float4(c0.y, c1.y, c2.y, c3.y);
    }
}

// ---------------------------------------------------------------------------
// attn_mean[b,q,k] = (1/H) * sum_h P[b,h,q,k]
// ---------------------------------------------------------------------------
__global__ __launch_bounds__(256) void attn_mean_kernel(
    const float* __restrict__ P, float* __restrict__ outm)
{
    size_t idx = (size_t)blockIdx.x * 256 + threadIdx.x;
    int k = (int)(idx & 1023);
    size_t t = idx >> 10;
    int q = (int)(t & 1023);
    int b = (int)(t >> 10);
    float s = 0.f;
    #pragma unroll
    for (int h = 0; h < HH; h++)
        s += P[((size_t)(b * HH + h) * SS + q) * SS + k];
    outm[idx] = s * (1.0f / HH);
}

// ---------------------------------------------------------------------------
// Host launcher
// ---------------------------------------------------------------------------
extern "C" void kernel_launch(void* const* d_in, const int* in_sizes, int n_in,
                              void* d_out, int out_size)
{
    const float* x     = (const float*)d_in[0];
    const float* w_in  = (const float*)d_in[1];
    const float* b_in  = (const float*)d_in[2];
    const float* w_out = (const float*)d_in[3];
    const float* b_out = (const float*)d_in[4];
    float* out = (float*)d_out;

    float *qkv, *P, *AO;
    cudaGetSymbolAddress((void**)&qkv, g_qkv);
    cudaGetSymbolAddress((void**)&P,   g_p);
    cudaGetSymbolAddress((void**)&AO,  g_ao);

    cudaFuncSetAttribute(attn_scores_softmax,
                         cudaFuncAttributeMaxDynamicSharedMemorySize, (int)SC_SMEM);

    // 1. QKV GEMM (tensor core, split-bf16) with fused q-scaling
    mma_gemm_bias<<<dim3(3 * DD / 128, MROWS / 128), 256>>>(
        x, w_in, b_in, qkv, MROWS, 3 * DD, DD, DD, QSCALE);

    // 2. scores + softmax -> P
    attn_scores_softmax<<<dim3(SS / QT, HH, BB), 256, SC_SMEM>>>(qkv, P);

    // 3. P @ V -> AO
    attn_pv<<<dim3(SS / 128, HH, BB), 256>>>(P, qkv, AO);

    // 4. head-mean
    attn_mean_kernel<<<(BB * SS * SS) / 256, 256>>>(P, out + (size_t)BB * SS * SS);

    // 5. output projection (tensor core, split-bf16)
    mma_gemm_bias<<<dim3(DD / 128, MROWS / 128), 256>>>(
        AO, w_out, b_out, out, MROWS, DD, DD, 0, 1.0f);
}

// round 4
// speedup vs baseline: 1.3940x; 1.3940x over previous
#include <cuda_runtime.h>
#include <cuda_bf16.h>
#include <cstdint>

// Problem constants
#define BB 4
#define SS 1024
#define DD 1024
#define HH 16
#define HD 64
#define MROWS (BB*SS)          // 4096
#define QSCALE 0.03125f        // 1024^-0.5

typedef unsigned long long u64;

// Scratch
__device__ float g_qkv[(size_t)MROWS * 3 * DD];              // [4096, 3072] fp32
__device__ float g_p[(size_t)BB * HH * SS * SS];             // [b,h,q,k] fp32
// pre-split bf16 operands
__device__ __nv_bfloat16 g_xh[(size_t)MROWS * DD],  g_xl[(size_t)MROWS * DD];
__device__ __nv_bfloat16 g_wih[(size_t)DD * 3 * DD], g_wil[(size_t)DD * 3 * DD];
__device__ __nv_bfloat16 g_woh[(size_t)DD * DD],    g_wol[(size_t)DD * DD];
__device__ __nv_bfloat16 g_aoh[(size_t)MROWS * DD], g_aol[(size_t)MROWS * DD];

// ---------------------------------------------------------------------------
// f32x2 packed-FMA helpers (Blackwell)
// ---------------------------------------------------------------------------
__device__ __forceinline__ void fma2(u64& d, u64 a, u64 b) {
    asm("fma.rn.f32x2 %0, %1, %2, %0;" : "+l"(d) : "l"(a), "l"(b));
}
__device__ __forceinline__ u64 pack2(float x, float y) {
    u64 r; asm("mov.b64 %0, {%1, %2};" : "=l"(r) : "f"(x), "f"(y)); return r;
}
__device__ __forceinline__ u64 dup2(float x) { return pack2(x, x); }
__device__ __forceinline__ float2 unpk(u64 v) {
    float2 r; asm("mov.b64 {%0, %1}, %2;" : "=f"(r.x), "=f"(r.y) : "l"(v)); return r;
}

// ---------------------------------------------------------------------------
// MMA / cp.async helpers
// ---------------------------------------------------------------------------
__device__ __forceinline__ void mma16816(float* d, const uint32_t* a, const uint32_t* b) {
    asm volatile(
        "mma.sync.aligned.m16n8k16.row.col.f32.bf16.bf16.f32 "
        "{%0,%1,%2,%3}, {%4,%5,%6,%7}, {%8,%9}, {%0,%1,%2,%3};"
        : "+f"(d[0]), "+f"(d[1]), "+f"(d[2]), "+f"(d[3])
        : "r"(a[0]), "r"(a[1]), "r"(a[2]), "r"(a[3]), "r"(b[0]), "r"(b[1]));
}
__device__ __forceinline__ void ldsm_x4(uint32_t* r, uint32_t addr) {
    asm volatile("ldmatrix.sync.aligned.m8n8.x4.shared.b16 {%0,%1,%2,%3}, [%4];"
                 : "=r"(r[0]), "=r"(r[1]), "=r"(r[2]), "=r"(r[3]) : "r"(addr));
}
__device__ __forceinline__ void ldsm_x2t(uint32_t* r, uint32_t addr) {
    asm volatile("ldmatrix.sync.aligned.m8n8.x2.trans.shared.b16 {%0,%1}, [%2];"
                 : "=r"(r[0]), "=r"(r[1]) : "r"(addr));
}
__device__ __forceinline__ void split_bf16(float v, __nv_bfloat16& h, __nv_bfloat16& l) {
    h = __float2bfloat16(v);
    l = __float2bfloat16(v - __bfloat162float(h));
}
__device__ __forceinline__ void cpa16(uint32_t s, const void* g) {
    asm volatile("cp.async.cg.shared.global [%0], [%1], 16;" :: "r"(s), "l"(g));
}
__device__ __forceinline__ void cp_commit() { asm volatile("cp.async.commit_group;"); }
template<int N> __device__ __forceinline__ void cp_wait() {
    asm volatile("cp.async.wait_group %0;" :: "n"(N));
}

// ---------------------------------------------------------------------------
// split kernel: fp32 -> (hi, lo) bf16
// ---------------------------------------------------------------------------
__global__ __launch_bounds__(256) void split_kernel(
    const float* __restrict__ in, __nv_bfloat16* __restrict__ hi,
    __nv_bfloat16* __restrict__ lo, int n4)
{
    int i = blockIdx.x * 256 + threadIdx.x;
    if (i >= n4) return;
    float4 v = ((const float4*)in)[i];
    __nv_bfloat16 h0, l0, h1, l1, h2, l2, h3, l3;
    split_bf16(v.x, h0, l0); split_bf16(v.y, h1, l1);
    split_bf16(v.z, h2, l2); split_bf16(v.w, h3, l3);
    ((__nv_bfloat162*)hi)[2 * i]     = __nv_bfloat162(h0, h1);
    ((__nv_bfloat162*)hi)[2 * i + 1] = __nv_bfloat162(h2, h3);
    ((__nv_bfloat162*)lo)[2 * i]     = __nv_bfloat162(l0, l1);
    ((__nv_bfloat162*)lo)[2 * i + 1] = __nv_bfloat162(l2, l3);
}

// ---------------------------------------------------------------------------
// Tensor-core GEMM on pre-split bf16 (3 MMA passes = ~fp32 accuracy).
// C[M,N] = A[M,K] @ B[K,N] + bias; cols < scale_cols get *scale.
// BM=BN=128, BK=32, 256 threads = 8 warps (4m x 2n). 3-stage cp.async pipe.
// ---------------------------------------------------------------------------
#define ASTR 40          // bf16 per A smem row (32+8)
#define BSTR 136         // bf16 per B smem row (128+8)
#define AH_OFF 0
#define AL_OFF 10240     // 128*40*2
#define BH_OFF 20480
#define BL_OFF 29184     // +32*136*2
#define STAGE_B 37888
#define NSTAGE 3
#define MMA_SMEM (STAGE_B * NSTAGE)

__global__ __launch_bounds__(256) void mma_gemm_presplit(
    const __nv_bfloat16* __restrict__ Ahg, const __nv_bfloat16* __restrict__ Alg,
    const __nv_bfloat16* __restrict__ Bhg, const __nv_bfloat16* __restrict__ Blg,
    const float* __restrict__ bias, float* __restrict__ C,
    int M, int N, int K, int scale_cols, float scale)
{
    extern __shared__ char dynsm[];
    uint32_t smbase = (uint32_t)__cvta_generic_to_shared(dynsm);

    int bx = blockIdx.x, by = blockIdx.y;
    int tid = threadIdx.x, lane = tid & 31, wid = tid >> 5;
    int wm = (wid & 3) * 32, wn = (wid >> 2) * 64;

    // cp.async load indices
    int ar = tid >> 2, ac = (tid & 3) * 8;     // A: 128 rows x 4 chunks (2 iters)
    int br = tid >> 4, bc = (tid & 15) * 8;    // B: 32 rows x 16 chunks (2 iters)

    // ldmatrix lane-offsets (bytes within a stage)
    uint32_t a_off = (uint32_t)((wm + (lane & 15)) * ASTR + (lane >> 4) * 8) * 2;
    uint32_t b_off = (uint32_t)((lane & 15) * BSTR + wn) * 2;

    float acc[2][8][4];
    #pragma unroll
    for (int i = 0; i < 2; i++)
        #pragma unroll
        for (int j = 0; j < 8; j++)
            #pragma unroll
            for (int c = 0; c < 4; c++) acc[i][j][c] = 0.f;

    const int nk = K >> 5;

    auto load_stage = [&](int st, int kt) {
        uint32_t sb = smbase + st * STAGE_B;
        #pragma unroll
        for (int i = 0; i < 2; i++) {
            int row = ar + i * 64;
            size_t g = (size_t)(by * 128 + row) * K + kt + ac;
            cpa16(sb + AH_OFF + (uint32_t)(row * ASTR + ac) * 2, Ahg + g);
            cpa16(sb + AL_OFF + (uint32_t)(row * ASTR + ac) * 2, Alg + g);
        }
        #pragma unroll
        for (int i = 0; i < 2; i++) {
            int row = br + i * 16;
            size_t g = (size_t)(kt + row) * N + bx * 128 + bc;
            cpa16(sb + BH_OFF + (uint32_t)(row * BSTR + bc) * 2, Bhg + g);
            cpa16(sb + BL_OFF + (uint32_t)(row * BSTR + bc) * 2, Blg + g);
        }
        cp_commit();
    };

    load_stage(0, 0);
    load_stage(1, 32);

    int st = 0;
    for (int i = 0; i < nk; i++) {
        if (i + 2 < nk) load_stage((st + 2) % NSTAGE, (i + 2) * 32);
        int rem = nk - 1 - i;
        if (rem >= 2) cp_wait<2>(); else if (rem == 1) cp_wait<1>(); else cp_wait<0>();
        __syncthreads();

        uint32_t sb = smbase + st * STAGE_B;
        #pragma unroll
        for (int ks = 0; ks < 2; ks++) {
            uint32_t ahf[2][4], alf[2][4];
            #pragma unroll
            for (int mi = 0; mi < 2; mi++) {
                uint32_t off = a_off + (uint32_t)(mi * 16 * ASTR + ks * 16) * 2;
                ldsm_x4(ahf[mi], sb + AH_OFF + off);
                ldsm_x4(alf[mi], sb + AL_OFF + off);
            }
            #pragma unroll
            for (int ni = 0; ni < 8; ni++) {
                uint32_t off = b_off + (uint32_t)(ks * 16 * BSTR + ni * 8) * 2;
                uint32_t bhf[2], blf[2];
                ldsm_x2t(bhf, sb + BH_OFF + off);
                ldsm_x2t(blf, sb + BL_OFF + off);
                #pragma unroll
                for (int mi = 0; mi < 2; mi++) {
                    mma16816(acc[mi][ni], ahf[mi], bhf);
                    mma16816(acc[mi][ni], ahf[mi], blf);
                    mma16816(acc[mi][ni], alf[mi], bhf);
                }
            }
        }
        __syncthreads();
        st = (st + 1) % NSTAGE;
    }

    // epilogue
    int group = lane >> 2, tig = lane & 3;
    bool sc = (bx * 128 < scale_cols);
    #pragma unroll
    for (int mi = 0; mi < 2; mi++) {
        int row0 = by * 128 + wm + mi * 16 + group;
        #pragma unroll
        for (int ni = 0; ni < 8; ni++) {
            int col = bx * 128 + wn + ni * 8 + tig * 2;
            float b0 = bias[col], b1 = bias[col + 1];
            float2 lo = make_float2(acc[mi][ni][0] + b0, acc[mi][ni][1] + b1);
            float2 hi = make_float2(acc[mi][ni][2] + b0, acc[mi][ni][3] + b1);
            if (sc) { lo.x *= scale; lo.y *= scale; hi.x *= scale; hi.y *= scale; }
            *(float2*)&C[(size_t)row0 * N + col]       = lo;
            *(float2*)&C[(size_t)(row0 + 8) * N + col] = hi;
        }
    }
}

// ---------------------------------------------------------------------------
// Fused scores + softmax per (b, h, 32-q tile). f32x2 inner product.
// ---------------------------------------------------------------------------
#define QT 32
#define KT2 256
#define SC_SMEM ((QT*SS + 64*36 + 64*KT2) * sizeof(float))

__global__ __launch_bounds__(256) void attn_scores_softmax(
    const float* __restrict__ qkv, float* __restrict__ P)
{
    extern __shared__ float sm[];
    float* Ssc = sm;                       // [QT][1024]
    float* Qs  = Ssc + QT * SS;            // [64][36]
    float* Ks  = Qs + 64 * 36;             // [64][256] swizzled

    int b  = blockIdx.z;
    int h  = blockIdx.y;
    int q0 = blockIdx.x * QT;
    int tid = threadIdx.x;
    int lane = tid & 31;
    int wq   = tid >> 5;

    for (int i = tid; i < QT * 64; i += 256) {
        int q = i >> 6, d = i & 63;
        Qs[d * 36 + q] = qkv[(size_t)(b * SS + q0 + q) * (3 * DD) + h * HD + d];
    }

    for (int kt = 0; kt < SS; kt += KT2) {
        __syncthreads();
        #pragma unroll
        for (int it = 0; it < 16; it++) {
            int i = tid + it * 256;
            int k = i >> 4, d4 = i & 15;
            float4 v = *(const float4*)&qkv[(size_t)(b * SS + kt + k) * (3 * DD) + DD + h * HD + d4 * 4];
            int sw = (d4 & 7) << 2;
            Ks[(d4 * 4 + 0) * KT2 + (k ^ sw)] = v.x;
            Ks[(d4 * 4 + 1) * KT2 + (k ^ sw)] = v.y;
            Ks[(d4 * 4 + 2) * KT2 + (k ^ sw)] = v.z;
            Ks[(d4 * 4 + 3) * KT2 + (k ^ sw)] = v.w;
        }
        __syncthreads();

        u64 acc[2][8];
        #pragma unroll
        for (int i = 0; i < 2; i++)
            #pragma unroll
            for (int j = 0; j < 8; j++) acc[i][j] = 0ull;

        #pragma unroll 4
        for (int d = 0; d < 64; d++) {
            ulonglong2 a = *(const ulonglong2*)&Qs[d * 36 + wq * 4];
            int sw = ((d >> 2) & 7) << 2;
            int kb = (lane * 4) ^ sw;
            float4 b0 = *(const float4*)&Ks[d * KT2 + kb];
            float4 b1 = *(const float4*)&Ks[d * KT2 + 128 + kb];
            u64 bd[8] = {dup2(b0.x), dup2(b0.y), dup2(b0.z), dup2(b0.w),
                         dup2(b1.x), dup2(b1.y), dup2(b1.z), dup2(b1.w)};
            #pragma unroll
            for (int j = 0; j < 8; j++) {
                fma2(acc[0][j], a.x, bd[j]);
                fma2(acc[1][j], a.y, bd[j]);
            }
        }

        #pragma unroll
        for (int rp = 0; rp < 2; rp++) {
            float2 c0 = unpk(acc[rp][0]), c1 = unpk(acc[rp][1]);
            float2 c2 = unpk(acc[rp][2]), c3 = unpk(acc[rp][3]);
            float2 c4 = unpk(acc[rp][4]), c5 = unpk(acc[rp][5]);
            float2 c6 = unpk(acc[rp][6]), c7 = unpk(acc[rp][7]);
            int rlo = wq * 4 + rp * 2, rhi = rlo + 1;
            *(float4*)&Ssc[rlo * SS + kt + lane * 4]       = make_float4(c0.x, c1.x, c2.x, c3.x);
            *(float4*)&Ssc[rlo * SS + kt + 128 + lane * 4] = make_float4(c4.x, c5.x, c6.x, c7.x);
            *(float4*)&Ssc[rhi * SS + kt + lane * 4]       = make_float4(c0.y, c1.y, c2.y, c3.y);
            *(float4*)&Ssc[rhi * SS + kt + 128 + lane * 4] = make_float4(c4.y, c5.y, c6.y, c7.y);
        }
    }
    __syncthreads();

    for (int r = wq * 4; r < wq * 4 + 4; r++) {
        const float* row = Ssc + r * SS;
        float v[32];
        float m = -1e30f;
        #pragma unroll
        for (int i = 0; i < 32; i++) {
            v[i] = row[lane + i * 32];
            m = fmaxf(m, v[i]);
        }
        #pragma unroll
        for (int o = 16; o; o >>= 1) m = fmaxf(m, __shfl_xor_sync(0xffffffffu, m, o));
        float s = 0.f;
        #pragma unroll
        for (int i = 0; i < 32; i++) { v[i] = __expf(v[i] - m); s += v[i]; }
        #pragma unroll
        for (int o = 16; o; o >>= 1) s += __shfl_xor_sync(0xffffffffu, s, o);
        float inv = 1.f / s;
        size_t base = ((size_t)(b * HH + h) * SS + q0 + r) * SS;
        #pragma unroll
        for (int i = 0; i < 32; i++) P[base + lane + i * 32] = v[i] * inv;
    }
}

// ---------------------------------------------------------------------------
// PV GEMM: AO = P @ V, writes AO as split bf16 (hi/lo) for the out-proj MMA.
// ---------------------------------------------------------------------------
__global__ __launch_bounds__(256) void attn_pv(
    const float* __restrict__ P, const float* __restrict__ qkv,
    __nv_bfloat16* __restrict__ AOh, __nv_bfloat16* __restrict__ AOl)
{
    __shared__ float Ps[64 * 132];
    __shared__ float Vs[64 * 68];

    int b  = blockIdx.z;
    int h  = blockIdx.y;
    int q0 = blockIdx.x * 128;
    int tid = threadIdx.x;
    int tx = tid & 15;
    int ty = tid >> 4;

    u64 acc[4][4];
    #pragma unroll
    for (int i = 0; i < 4; i++)
        #pragma unroll
        for (int j = 0; j < 4; j++) acc[i][j] = 0ull;

    for (int kt = 0; kt < SS; kt += 64) {
        __syncthreads();
        #pragma unroll
        for (int it = 0; it < 8; it++) {
            int i = tid + it * 256;
            int q = i >> 4, k4 = i & 15;
            float4 pv = *(const float4*)&P[((size_t)(b * HH + h) * SS + q0 + q) * SS + kt + k4 * 4];
            Ps[(k4 * 4 + 0) * 132 + q] = pv.x;
            Ps[(k4 * 4 + 1) * 132 + q] = pv.y;
            Ps[(k4 * 4 + 2) * 132 + q] = pv.z;
            Ps[(k4 * 4 + 3) * 132 + q] = pv.w;
        }
        #pragma unroll
        for (int it = 0; it < 4; it++) {
            int i = tid + it * 256;
            int k = i >> 4, d4 = i & 15;
            *(float4*)&Vs[k * 68 + d4 * 4] =
                *(const float4*)&qkv[(size_t)(b * SS + kt + k) * (3 * DD) + 2 * DD + h * HD + d4 * 4];
        }
        __syncthreads();

        #pragma unroll 4
        for (int k = 0; k < 64; k++) {
            ulonglong2 p0 = *(const ulonglong2*)&Ps[k * 132 + ty * 8];
            ulonglong2 p1 = *(const ulonglong2*)&Ps[k * 132 + ty * 8 + 4];
            u64 am[4] = {p0.x, p0.y, p1.x, p1.y};
            float4 v = *(const float4*)&Vs[k * 68 + tx * 4];
            u64 vd[4] = {dup2(v.x), dup2(v.y), dup2(v.z), dup2(v.w)};
            #pragma unroll
            for (int i = 0; i < 4; i++)
                #pragma unroll
                for (int j = 0; j < 4; j++)
                    fma2(acc[i][j], am[i], vd[j]);
        }
    }

    #pragma unroll
    for (int qp = 0; qp < 4; qp++) {
        float2 c0 = unpk(acc[qp][0]), c1 = unpk(acc[qp][1]);
        float2 c2 = unpk(acc[qp][2]), c3 = unpk(acc[qp][3]);
        float vals[2][4] = {{c0.x, c1.x, c2.x, c3.x}, {c0.y, c1.y, c2.y, c3.y}};
        #pragma unroll
        for (int r = 0; r < 2; r++) {
            int q = q0 + ty * 8 + qp * 2 + r;
            size_t off = (size_t)(b * SS + q) * DD + h * HD + tx * 4;
            __nv_bfloat16 hh[4], ll[4];
            #pragma unroll
            for (int j = 0; j < 4; j++) split_bf16(vals[r][j], hh[j], ll[j]);
            *(__nv_bfloat162*)&AOh[off]     = __nv_bfloat162(hh[0], hh[1]);
            *(__nv_bfloat162*)&AOh[off + 2] = __nv_bfloat162(hh[2], hh[3]);
            *(__nv_bfloat162*)&AOl[off]     = __nv_bfloat162(ll[0], ll[1]);
            *(__nv_bfloat162*)&AOl[off + 2] = __nv_bfloat162(ll[2], ll[3]);
        }
    }
}

// ---------------------------------------------------------------------------
// attn_mean[b,q,k] = (1/H) * sum_h P[b,h,q,k]
// ---------------------------------------------------------------------------
__global__ __launch_bounds__(256) void attn_mean_kernel(
    const float* __restrict__ P, float* __restrict__ outm)
{
    size_t idx = (size_t)blockIdx.x * 256 + threadIdx.x;
    int k = (int)(idx & 1023);
    size_t t = idx >> 10;
    int q = (int)(t & 1023);
    int b = (int)(t >> 10);
    float s = 0.f;
    #pragma unroll
    for (int h = 0; h < HH; h++)
        s += P[((size_t)(b * HH + h) * SS + q) * SS + k];
    outm[idx] = s * (1.0f / HH);
}

// ---------------------------------------------------------------------------
// Host launcher
// ---------------------------------------------------------------------------
extern "C" void kernel_launch(void* const* d_in, const int* in_sizes, int n_in,
                              void* d_out, int out_size)
{
    const float* x     = (const float*)d_in[0];
    const float* w_in  = (const float*)d_in[1];
    const float* b_in  = (const float*)d_in[2];
    const float* w_out = (const float*)d_in[3];
    const float* b_out = (const float*)d_in[4];
    float* out = (float*)d_out;

    float *qkv, *P;
    __nv_bfloat16 *xh, *xl, *wih, *wil, *woh, *wol, *aoh, *aol;
    cudaGetSymbolAddress((void**)&qkv, g_qkv);
    cudaGetSymbolAddress((void**)&P,   g_p);
    cudaGetSymbolAddress((void**)&xh,  g_xh);
    cudaGetSymbolAddress((void**)&xl,  g_xl);
    cudaGetSymbolAddress((void**)&wih, g_wih);
    cudaGetSymbolAddress((void**)&wil, g_wil);
    cudaGetSymbolAddress((void**)&woh, g_woh);
    cudaGetSymbolAddress((void**)&wol, g_wol);
    cudaGetSymbolAddress((void**)&aoh, g_aoh);
    cudaGetSymbolAddress((void**)&aol, g_aol);

    cudaFuncSetAttribute(attn_scores_softmax,
                         cudaFuncAttributeMaxDynamicSharedMemorySize, (int)SC_SMEM);
    cudaFuncSetAttribute(mma_gemm_presplit,
                         cudaFuncAttributeMaxDynamicSharedMemorySize, MMA_SMEM);

    // 0. pre-split operands into bf16 hi/lo
    split_kernel<<<(MROWS * DD / 4 + 255) / 256, 256>>>(x, xh, xl, MROWS * DD / 4);
    split_kernel<<<(DD * 3 * DD / 4 + 255) / 256, 256>>>(w_in, wih, wil, DD * 3 * DD / 4);
    split_kernel<<<(DD * DD / 4 + 255) / 256, 256>>>(w_out, woh, wol, DD * DD / 4);

    // 1. QKV GEMM (tensor core, pre-split, pipelined) + fused q-scaling
    mma_gemm_presplit<<<dim3(3 * DD / 128, MROWS / 128), 256, MMA_SMEM>>>(
        xh, xl, wih, wil, b_in, qkv, MROWS, 3 * DD, DD, DD, QSCALE);

    // 2. scores + softmax -> P
    attn_scores_softmax<<<dim3(SS / QT, HH, BB), 256, SC_SMEM>>>(qkv, P);

    // 3. P @ V -> AO (split bf16)
    attn_pv<<<dim3(SS / 128, HH, BB), 256>>>(P, qkv, aoh, aol);

    // 4. head-mean
    attn_mean_kernel<<<(BB * SS * SS) / 256, 256>>>(P, out + (size_t)BB * SS * SS);

    // 5. output projection (tensor core, pre-split)
    mma_gemm_presplit<<<dim3(DD / 128, MROWS / 128), 256, MMA_SMEM>>>(
        aoh, aol, woh, wol, b_out, out, MROWS, DD, DD, 0, 1.0f);
}

// round 5
// speedup vs baseline: 2.2209x; 1.5932x over previous
#include <cuda_runtime.h>
#include <cuda_bf16.h>
#include <cstdint>

// Problem constants
#define BB 4
#define SS 1024
#define DD 1024
#define HH 16
#define HD 64
#define MROWS (BB*SS)          // 4096
#define QSCALE 0.03125f        // 1024^-0.5

// ---------------------------------------------------------------------------
// Scratch (static device arrays; no runtime alloc)
// ---------------------------------------------------------------------------
__device__ __nv_bfloat16 g_xh[(size_t)MROWS * DD],   g_xl[(size_t)MROWS * DD];
__device__ __nv_bfloat16 g_wih[(size_t)DD * 3 * DD], g_wil[(size_t)DD * 3 * DD];
__device__ __nv_bfloat16 g_woh[(size_t)DD * DD],     g_wol[(size_t)DD * DD];
__device__ __nv_bfloat16 g_qh[(size_t)BB*HH*SS*HD],  g_ql[(size_t)BB*HH*SS*HD];
__device__ __nv_bfloat16 g_kh[(size_t)BB*HH*SS*HD],  g_kl[(size_t)BB*HH*SS*HD];
__device__ __nv_bfloat16 g_vh[(size_t)BB*HH*SS*HD],  g_vl[(size_t)BB*HH*SS*HD];
__device__ __nv_bfloat16 g_ph[(size_t)BB*HH*SS*SS],  g_pl[(size_t)BB*HH*SS*SS];
__device__ __nv_bfloat16 g_aoh[(size_t)MROWS * DD],  g_aol[(size_t)MROWS * DD];

// ---------------------------------------------------------------------------
// MMA / ldmatrix / cp.async helpers
// ---------------------------------------------------------------------------
__device__ __forceinline__ void mma16816(float* d, const uint32_t* a, const uint32_t* b) {
    asm volatile(
        "mma.sync.aligned.m16n8k16.row.col.f32.bf16.bf16.f32 "
        "{%0,%1,%2,%3}, {%4,%5,%6,%7}, {%8,%9}, {%0,%1,%2,%3};"
        : "+f"(d[0]), "+f"(d[1]), "+f"(d[2]), "+f"(d[3])
        : "r"(a[0]), "r"(a[1]), "r"(a[2]), "r"(a[3]), "r"(b[0]), "r"(b[1]));
}
__device__ __forceinline__ void ldsm_x4(uint32_t* r, uint32_t addr) {
    asm volatile("ldmatrix.sync.aligned.m8n8.x4.shared.b16 {%0,%1,%2,%3}, [%4];"
                 : "=r"(r[0]), "=r"(r[1]), "=r"(r[2]), "=r"(r[3]) : "r"(addr));
}
__device__ __forceinline__ void ldsm_x2t(uint32_t* r, uint32_t addr) {
    asm volatile("ldmatrix.sync.aligned.m8n8.x2.trans.shared.b16 {%0,%1}, [%2];"
                 : "=r"(r[0]), "=r"(r[1]) : "r"(addr));
}
__device__ __forceinline__ void split_bf16(float v, __nv_bfloat16& h, __nv_bfloat16& l) {
    h = __float2bfloat16(v);
    l = __float2bfloat16(v - __bfloat162float(h));
}
__device__ __forceinline__ void cpa16(uint32_t s, const void* g) {
    asm volatile("cp.async.cg.shared.global [%0], [%1], 16;" :: "r"(s), "l"(g));
}
__device__ __forceinline__ void cp_commit() { asm volatile("cp.async.commit_group;"); }
template<int N> __device__ __forceinline__ void cp_wait() {
    asm volatile("cp.async.wait_group %0;" :: "n"(N));
}

// ---------------------------------------------------------------------------
// split kernel: fp32 -> (hi, lo) bf16
// ---------------------------------------------------------------------------
__global__ __launch_bounds__(256) void split_kernel(
    const float* __restrict__ in, __nv_bfloat16* __restrict__ hi,
    __nv_bfloat16* __restrict__ lo, int n4)
{
    int i = blockIdx.x * 256 + threadIdx.x;
    if (i >= n4) return;
    float4 v = ((const float4*)in)[i];
    __nv_bfloat16 h0, l0, h1, l1, h2, l2, h3, l3;
    split_bf16(v.x, h0, l0); split_bf16(v.y, h1, l1);
    split_bf16(v.z, h2, l2); split_bf16(v.w, h3, l3);
    ((__nv_bfloat162*)hi)[2 * i]     = __nv_bfloat162(h0, h1);
    ((__nv_bfloat162*)hi)[2 * i + 1] = __nv_bfloat162(h2, h3);
    ((__nv_bfloat162*)lo)[2 * i]     = __nv_bfloat162(l0, l1);
    ((__nv_bfloat162*)lo)[2 * i + 1] = __nv_bfloat162(l2, l3);
}

// ---------------------------------------------------------------------------
// GEMM tile constants (BM=BN=128, BK=32, 8 warps = 4m x 2n), 2-stage cp.async
// ---------------------------------------------------------------------------
#define ASTR 40
#define BSTR 136
#define AH_OFF 0
#define AL_OFF 10240
#define BH_OFF 20480
#define BL_OFF 29184
#define STAGE_B 37888
#define GEMM_SMEM (STAGE_B * 2)

#define GEMM_PROLOG \
    extern __shared__ char dynsm[]; \
    uint32_t smbase = (uint32_t)__cvta_generic_to_shared(dynsm); \
    int bx = blockIdx.x, by = blockIdx.y; \
    int tid = threadIdx.x, lane = tid & 31, wid = tid >> 5; \
    int wm = (wid & 3) * 32, wn = (wid >> 2) * 64; \
    int ar = tid >> 2, ac = (tid & 3) * 8; \
    int br = tid >> 4, bc = (tid & 15) * 8; \
    uint32_t a_off = (uint32_t)((wm + (lane & 15)) * ASTR + (lane >> 4) * 8) * 2; \
    uint32_t b_off = (uint32_t)((lane & 15) * BSTR + wn) * 2; \
    float acc[2][8][4]; \
    _Pragma("unroll") for (int i = 0; i < 2; i++) \
        _Pragma("unroll") for (int j = 0; j < 8; j++) \
            _Pragma("unroll") for (int c = 0; c < 4; c++) acc[i][j][c] = 0.f; \
    const int nk = K >> 5; \
    auto load_stage = [&](int st, int kt) { \
        uint32_t sb = smbase + st * STAGE_B; \
        _Pragma("unroll") for (int i = 0; i < 2; i++) { \
            int row = ar + i * 64; \
            size_t g = (size_t)(by * 128 + row) * K + kt + ac; \
            cpa16(sb + AH_OFF + (uint32_t)(row * ASTR + ac) * 2, Ahg + g); \
            cpa16(sb + AL_OFF + (uint32_t)(row * ASTR + ac) * 2, Alg + g); \
        } \
        _Pragma("unroll") for (int i = 0; i < 2; i++) { \
            int row = br + i * 16; \
            size_t g = (size_t)(kt + row) * N + bx * 128 + bc; \
            cpa16(sb + BH_OFF + (uint32_t)(row * BSTR + bc) * 2, Bhg + g); \
            cpa16(sb + BL_OFF + (uint32_t)(row * BSTR + bc) * 2, Blg + g); \
        } \
        cp_commit(); \
    }; \
    load_stage(0, 0); \
    load_stage(1, 32); \
    for (int i = 0; i < nk; i++) { \
        if (i < nk - 1) cp_wait<1>(); else cp_wait<0>(); \
        __syncthreads(); \
        uint32_t sb = smbase + (i & 1) * STAGE_B; \
        _Pragma("unroll") for (int ks = 0; ks < 2; ks++) { \
            uint32_t ahf[2][4], alf[2][4]; \
            _Pragma("unroll") for (int mi = 0; mi < 2; mi++) { \
                uint32_t off = a_off + (uint32_t)(mi * 16 * ASTR + ks * 16) * 2; \
                ldsm_x4(ahf[mi], sb + AH_OFF + off); \
                ldsm_x4(alf[mi], sb + AL_OFF + off); \
            } \
            _Pragma("unroll") for (int ni = 0; ni < 8; ni++) { \
                uint32_t off = b_off + (uint32_t)(ks * 16 * BSTR + ni * 8) * 2; \
                uint32_t bhf[2], blf[2]; \
                ldsm_x2t(bhf, sb + BH_OFF + off); \
                ldsm_x2t(blf, sb + BL_OFF + off); \
                _Pragma("unroll") for (int mi = 0; mi < 2; mi++) { \
                    mma16816(acc[mi][ni], ahf[mi], bhf); \
                    mma16816(acc[mi][ni], ahf[mi], blf); \
                    mma16816(acc[mi][ni], alf[mi], bhf); \
                } \
            } \
        } \
        __syncthreads(); \
        if (i + 2 < nk) load_stage((i + 2) & 1, (i + 2) * 32); \
    }

// ---------------------------------------------------------------------------
// QKV GEMM: writes q (scaled), k, v as split bf16 in [b,h,s,d] layout
// ---------------------------------------------------------------------------
__global__ __launch_bounds__(256, 2) void mma_gemm_qkv(
    const __nv_bfloat16* __restrict__ Ahg, const __nv_bfloat16* __restrict__ Alg,
    const __nv_bfloat16* __restrict__ Bhg, const __nv_bfloat16* __restrict__ Blg,
    const float* __restrict__ bias,
    __nv_bfloat16* __restrict__ qh, __nv_bfloat16* __restrict__ ql,
    __nv_bfloat16* __restrict__ kh, __nv_bfloat16* __restrict__ kl,
    __nv_bfloat16* __restrict__ vh, __nv_bfloat16* __restrict__ vl,
    int M, int N, int K)
{
    GEMM_PROLOG

    // epilogue: route to q/k/v split arrays
    int part = (bx * 128) >> 10;                        // uniform per CTA
    __nv_bfloat16* dh = part == 0 ? qh : (part == 1 ? kh : vh);
    __nv_bfloat16* dl = part == 0 ? ql : (part == 1 ? kl : vl);
    float mul = part == 0 ? QSCALE : 1.0f;
    int head = ((bx * 128 + wn) & 1023) >> 6;           // uniform per warp
    int bq = (by * 128) >> 10;
    int group = lane >> 2, tig = lane & 3;
    #pragma unroll
    for (int mi = 0; mi < 2; mi++) {
        int s0 = ((by * 128) & 1023) + wm + mi * 16 + group;
        #pragma unroll
        for (int ni = 0; ni < 8; ni++) {
            int col = bx * 128 + wn + ni * 8 + tig * 2;
            int d = ni * 8 + tig * 2;
            float b0 = bias[col], b1 = bias[col + 1];
            float v00 = (acc[mi][ni][0] + b0) * mul, v01 = (acc[mi][ni][1] + b1) * mul;
            float v10 = (acc[mi][ni][2] + b0) * mul, v11 = (acc[mi][ni][3] + b1) * mul;
            size_t o0 = ((size_t)(bq * HH + head) * SS + s0) * HD + d;
            size_t o1 = o0 + 8 * HD;
            __nv_bfloat16 h0, l0, h1, l1;
            split_bf16(v00, h0, l0); split_bf16(v01, h1, l1);
            *(__nv_bfloat162*)&dh[o0] = __nv_bfloat162(h0, h1);
            *(__nv_bfloat162*)&dl[o0] = __nv_bfloat162(l0, l1);
            split_bf16(v10, h0, l0); split_bf16(v11, h1, l1);
            *(__nv_bfloat162*)&dh[o1] = __nv_bfloat162(h0, h1);
            *(__nv_bfloat162*)&dl[o1] = __nv_bfloat162(l0, l1);
        }
    }
}

// ---------------------------------------------------------------------------
// Out-projection GEMM: fp32 output + bias
// ---------------------------------------------------------------------------
__global__ __launch_bounds__(256, 2) void mma_gemm_out(
    const __nv_bfloat16* __restrict__ Ahg, const __nv_bfloat16* __restrict__ Alg,
    const __nv_bfloat16* __restrict__ Bhg, const __nv_bfloat16* __restrict__ Blg,
    const float* __restrict__ bias, float* __restrict__ C,
    int M, int N, int K)
{
    GEMM_PROLOG

    int group = lane >> 2, tig = lane & 3;
    #pragma unroll
    for (int mi = 0; mi < 2; mi++) {
        int row0 = by * 128 + wm + mi * 16 + group;
        #pragma unroll
        for (int ni = 0; ni < 8; ni++) {
            int col = bx * 128 + wn + ni * 8 + tig * 2;
            float b0 = bias[col], b1 = bias[col + 1];
            *(float2*)&C[(size_t)row0 * N + col] =
                make_float2(acc[mi][ni][0] + b0, acc[mi][ni][1] + b1);
            *(float2*)&C[(size_t)(row0 + 8) * N + col] =
                make_float2(acc[mi][ni][2] + b0, acc[mi][ni][3] + b1);
        }
    }
}

// ---------------------------------------------------------------------------
// Scores + softmax (MMA): per (b,h,32q). S = Q K^T (3-pass split MMA),
// softmax in smem, write P as split bf16.
// smem: Ssc fp32[32][1032] | Qh/Ql [32][72] | K stages x2 (Kh/Kl [128][72])
// ---------------------------------------------------------------------------
#define SC2_QH 132096
#define SC2_QL 136704
#define SC2_K  141312
#define SC2_KSTAGE 36864
#define SC2_SMEM 215040

__global__ __launch_bounds__(256) void attn_scores_mma(
    const __nv_bfloat16* __restrict__ qh, const __nv_bfloat16* __restrict__ ql,
    const __nv_bfloat16* __restrict__ kh, const __nv_bfloat16* __restrict__ kl,
    __nv_bfloat16* __restrict__ Ph, __nv_bfloat16* __restrict__ Pl)
{
    extern __shared__ char dynsm[];
    float* Ssc = (float*)dynsm;
    uint32_t smbase = (uint32_t)__cvta_generic_to_shared(dynsm);

    int b = blockIdx.z, h = blockIdx.y, q0 = blockIdx.x * 32;
    int tid = threadIdx.x, lane = tid & 31, wid = tid >> 5;
    int wm = (wid & 1) * 16;        // 2 warps over m=32
    int wn = (wid >> 1) * 32;       // 4 groups over n=128

    // load Q tile 32x64 (hi/lo)
    {
        size_t qb = ((size_t)(b * HH + h) * SS + q0) * HD;
        int row = tid >> 3, c8 = (tid & 7) * 8;
        *(uint4*)(dynsm + SC2_QH + (row * 72 + c8) * 2) = *(const uint4*)&qh[qb + row * 64 + c8];
        *(uint4*)(dynsm + SC2_QL + (row * 72 + c8) * 2) = *(const uint4*)&ql[qb + row * 64 + c8];
    }

    auto load_k = [&](int st, int kt) {
        uint32_t kb = smbase + SC2_K + st * SC2_KSTAGE;
        size_t gb = ((size_t)(b * HH + h) * SS + kt) * HD;
        #pragma unroll
        for (int it = 0; it < 4; it++) {
            int idx = tid + it * 256;
            int row = idx >> 3, c8 = (idx & 7) * 8;
            cpa16(kb + (uint32_t)(row * 72 + c8) * 2, kh + gb + row * 64 + c8);
            cpa16(kb + 18432 + (uint32_t)(row * 72 + c8) * 2, kl + gb + row * 64 + c8);
        }
        cp_commit();
    };
    load_k(0, 0);
    load_k(1, 128);

    // fragment addresses
    uint32_t aq_off = (uint32_t)((wm + (lane & 15)) * 72 + (lane >> 4) * 8) * 2;
    int rr_ = lane & 7, halfk = (lane >> 3) & 1, q2 = lane >> 4;
    uint32_t bk_off = (uint32_t)((wn + q2 * 8 + rr_) * 72 + halfk * 8) * 2;

    for (int i = 0; i < 8; i++) {
        if (i < 7) cp_wait<1>(); else cp_wait<0>();
        __syncthreads();
        uint32_t kb = smbase + SC2_K + (i & 1) * SC2_KSTAGE;

        float acc[4][4];
        #pragma unroll
        for (int a = 0; a < 4; a++)
            #pragma unroll
            for (int c = 0; c < 4; c++) acc[a][c] = 0.f;

        #pragma unroll
        for (int ks = 0; ks < 4; ks++) {
            uint32_t ahf[4], alf[4];
            ldsm_x4(ahf, smbase + SC2_QH + aq_off + ks * 32);
            ldsm_x4(alf, smbase + SC2_QL + aq_off + ks * 32);
            #pragma unroll
            for (int ni2 = 0; ni2 < 2; ni2++) {
                uint32_t boff = bk_off + (uint32_t)(ni2 * 16 * 72 + ks * 16) * 2;
                uint32_t bhf[4], blf[4];
                ldsm_x4(bhf, kb + boff);            // hi: [m0,m1]=n..n+8 k0-15, [m2,m3]=n+8..16
                ldsm_x4(blf, kb + 18432 + boff);
                mma16816(acc[ni2*2],   ahf, bhf);
                mma16816(acc[ni2*2],   ahf, blf);
                mma16816(acc[ni2*2],   alf, bhf);
                mma16816(acc[ni2*2+1], ahf, bhf + 2);
                mma16816(acc[ni2*2+1], ahf, blf + 2);
                mma16816(acc[ni2*2+1], alf, bhf + 2);
            }
        }

        // store score tile to smem
        int kt = i * 128;
        int group = lane >> 2, tig = lane & 3;
        #pragma unroll
        for (int ni = 0; ni < 4; ni++) {
            int row = wm + group;
            int col = kt + wn + ni * 8 + tig * 2;
            *(float2*)&Ssc[row * 1032 + col]       = make_float2(acc[ni][0], acc[ni][1]);
            *(float2*)&Ssc[(row + 8) * 1032 + col] = make_float2(acc[ni][2], acc[ni][3]);
        }
        __syncthreads();
        if (i + 2 < 8) load_k((i + 2) & 1, (i + 2) * 128);
    }

    // softmax: 8 warps x 4 rows, write split-bf16 P
    for (int rr = 0; rr < 4; rr++) {
        int row = wid * 4 + rr;
        float2 v2[16];
        float m = -1e30f;
        #pragma unroll
        for (int i2 = 0; i2 < 16; i2++) {
            v2[i2] = *(float2*)&Ssc[row * 1032 + (lane + i2 * 32) * 2];
            m = fmaxf(m, fmaxf(v2[i2].x, v2[i2].y));
        }
        #pragma unroll
        for (int o = 16; o; o >>= 1) m = fmaxf(m, __shfl_xor_sync(0xffffffffu, m, o));
        float s = 0.f;
        #pragma unroll
        for (int i2 = 0; i2 < 16; i2++) {
            v2[i2].x = __expf(v2[i2].x - m);
            v2[i2].y = __expf(v2[i2].y - m);
            s += v2[i2].x + v2[i2].y;
        }
        #pragma unroll
        for (int o = 16; o; o >>= 1) s += __shfl_xor_sync(0xffffffffu, s, o);
        float inv = 1.f / s;
        size_t gb = ((size_t)(b * HH + h) * SS + q0 + row) * SS;
        #pragma unroll
        for (int i2 = 0; i2 < 16; i2++) {
            float p0 = v2[i2].x * inv, p1 = v2[i2].y * inv;
            __nv_bfloat16 h0, l0, h1, l1;
            split_bf16(p0, h0, l0); split_bf16(p1, h1, l1);
            size_t o = gb + (size_t)(lane + i2 * 32) * 2;
            *(__nv_bfloat162*)&Ph[o] = __nv_bfloat162(h0, h1);
            *(__nv_bfloat162*)&Pl[o] = __nv_bfloat162(l0, l1);
        }
    }
}

// ---------------------------------------------------------------------------
// PV (MMA): AO = P @ V per (b,h,128q), 3-pass split. AO written split-bf16.
// smem stages x2: Ph/Pl [128][72] + Vh/Vl [64][72]
// ---------------------------------------------------------------------------
#define PV_PH 0
#define PV_PL 18432
#define PV_VH 36864
#define PV_VL 46080
#define PV_STAGE 55296
#define PV_SMEM 110592

__global__ __launch_bounds__(256) void attn_pv_mma(
    const __nv_bfloat16* __restrict__ Ph, const __nv_bfloat16* __restrict__ Pl,
    const __nv_bfloat16* __restrict__ vh, const __nv_bfloat16* __restrict__ vl,
    __nv_bfloat16* __restrict__ AOh, __nv_bfloat16* __restrict__ AOl)
{
    extern __shared__ char dynsm[];
    uint32_t smbase = (uint32_t)__cvta_generic_to_shared(dynsm);

    int b = blockIdx.z, h = blockIdx.y, q0 = blockIdx.x * 128;
    int tid = threadIdx.x, lane = tid & 31, wid = tid >> 5;

    auto load_stage = [&](int st, int kt) {
        uint32_t sb = smbase + st * PV_STAGE;
        size_t pb = ((size_t)(b * HH + h) * SS + q0) * SS + kt;
        #pragma unroll
        for (int it = 0; it < 4; it++) {
            int idx = tid + it * 256;
            int row = idx >> 3, c8 = (idx & 7) * 8;
            cpa16(sb + PV_PH + (uint32_t)(row * 72 + c8) * 2, Ph + pb + (size_t)row * SS + c8);
            cpa16(sb + PV_PL + (uint32_t)(row * 72 + c8) * 2, Pl + pb + (size_t)row * SS + c8);
        }
        size_t vb = ((size_t)(b * HH + h) * SS + kt) * HD;
        #pragma unroll
        for (int it = 0; it < 2; it++) {
            int idx = tid + it * 256;
            int row = idx >> 3, c8 = (idx & 7) * 8;
            cpa16(sb + PV_VH + (uint32_t)(row * 72 + c8) * 2, vh + vb + row * 64 + c8);
            cpa16(sb + PV_VL + (uint32_t)(row * 72 + c8) * 2, vl + vb + row * 64 + c8);
        }
        cp_commit();
    };

    float acc[8][4];
    #pragma unroll
    for (int a = 0; a < 8; a++)
        #pragma unroll
        for (int c = 0; c < 4; c++) acc[a][c] = 0.f;

    uint32_t ap_off = (uint32_t)((wid * 16 + (lane & 15)) * 72 + (lane >> 4) * 8) * 2;
    uint32_t bv_off = (uint32_t)((lane & 15) * 72) * 2;

    load_stage(0, 0);
    load_stage(1, 64);

    for (int i = 0; i < 16; i++) {
        if (i < 15) cp_wait<1>(); else cp_wait<0>();
        __syncthreads();
        uint32_t sb = smbase + (i & 1) * PV_STAGE;
        #pragma unroll
        for (int ks = 0; ks < 4; ks++) {
            uint32_t ahf[4], alf[4];
            ldsm_x4(ahf, sb + PV_PH + ap_off + ks * 32);
            ldsm_x4(alf, sb + PV_PL + ap_off + ks * 32);
            #pragma unroll
            for (int ni = 0; ni < 8; ni++) {
                uint32_t off = bv_off + (uint32_t)(ks * 16 * 72 + ni * 8) * 2;
                uint32_t bhf[2], blf[2];
                ldsm_x2t(bhf, sb + PV_VH + off);
                ldsm_x2t(blf, sb + PV_VL + off);
                mma16816(acc[ni], ahf, bhf);
                mma16816(acc[ni], ahf, blf);
                mma16816(acc[ni], alf, bhf);
            }
        }
        __syncthreads();
        if (i + 2 < 16) load_stage((i + 2) & 1, (i + 2) * 64);
    }

    int group = lane >> 2, tig = lane & 3;
    #pragma unroll
    for (int ni = 0; ni < 8; ni++) {
        int d = ni * 8 + tig * 2;
        int r0 = q0 + wid * 16 + group;
        size_t o0 = (size_t)(b * SS + r0) * DD + h * HD + d;
        size_t o1 = o0 + (size_t)8 * DD;
        __nv_bfloat16 h0, l0, h1, l1;
        split_bf16(acc[ni][0], h0, l0); split_bf16(acc[ni][1], h1, l1);
        *(__nv_bfloat162*)&AOh[o0] = __nv_bfloat162(h0, h1);
        *(__nv_bfloat162*)&AOl[o0] = __nv_bfloat162(l0, l1);
        split_bf16(acc[ni][2], h0, l0); split_bf16(acc[ni][3], h1, l1);
        *(__nv_bfloat162*)&AOh[o1] = __nv_bfloat162(h0, h1);
        *(__nv_bfloat162*)&AOl[o1] = __nv_bfloat162(l0, l1);
    }
}

// ---------------------------------------------------------------------------
// attn_mean[b,q,k] = (1/H) * sum_h (Ph + Pl)
// ---------------------------------------------------------------------------
__global__ __launch_bounds__(256) void attn_mean_kernel(
    const __nv_bfloat16* __restrict__ Ph, const __nv_bfloat16* __restrict__ Pl,
    float* __restrict__ outm)
{
    size_t g = (size_t)blockIdx.x * 256 + threadIdx.x;    // 8-elem groups
    int k8 = (int)(g & 127);
    size_t t = g >> 7;
    int q = (int)(t & 1023);
    int b = (int)(t >> 10);
    size_t k = (size_t)k8 * 8;

    float acc8[8];
    #pragma unroll
    for (int j = 0; j < 8; j++) acc8[j] = 0.f;
    #pragma unroll
    for (int h = 0; h < HH; h++) {
        size_t off = ((size_t)(b * HH + h) * SS + q) * SS + k;
        uint4 vh4 = *(const uint4*)&Ph[off];
        uint4 vl4 = *(const uint4*)&Pl[off];
        const uint32_t* ph = (const uint32_t*)&vh4;
        const uint32_t* pl = (const uint32_t*)&vl4;
        #pragma unroll
        for (int j = 0; j < 4; j++) {
            __nv_bfloat162 hh = *(__nv_bfloat162*)&ph[j];
            __nv_bfloat162 ll = *(__nv_bfloat162*)&pl[j];
            acc8[2*j]   += __low2float(hh)  + __low2float(ll);
            acc8[2*j+1] += __high2float(hh) + __high2float(ll);
        }
    }
    size_t ob = ((size_t)(b * SS + q)) * SS + k;
    float4 o0 = make_float4(acc8[0], acc8[1], acc8[2], acc8[3]);
    float4 o1 = make_float4(acc8[4], acc8[5], acc8[6], acc8[7]);
    const float inv = 1.0f / HH;
    o0.x *= inv; o0.y *= inv; o0.z *= inv; o0.w *= inv;
    o1.x *= inv; o1.y *= inv; o1.z *= inv; o1.w *= inv;
    *(float4*)&outm[ob]     = o0;
    *(float4*)&outm[ob + 4] = o1;
}

// ---------------------------------------------------------------------------
// Host launcher
// ---------------------------------------------------------------------------
extern "C" void kernel_launch(void* const* d_in, const int* in_sizes, int n_in,
                              void* d_out, int out_size)
{
    const float* x     = (const float*)d_in[0];
    const float* w_in  = (const float*)d_in[1];
    const float* b_in  = (const float*)d_in[2];
    const float* w_out = (const float*)d_in[3];
    const float* b_out = (const float*)d_in[4];
    float* out = (float*)d_out;

    __nv_bfloat16 *xh, *xl, *wih, *wil, *woh, *wol;
    __nv_bfloat16 *qh, *ql, *kh, *kl, *vh, *vl, *ph, *pl, *aoh, *aol;
    cudaGetSymbolAddress((void**)&xh,  g_xh);
    cudaGetSymbolAddress((void**)&xl,  g_xl);
    cudaGetSymbolAddress((void**)&wih, g_wih);
    cudaGetSymbolAddress((void**)&wil, g_wil);
    cudaGetSymbolAddress((void**)&woh, g_woh);
    cudaGetSymbolAddress((void**)&wol, g_wol);
    cudaGetSymbolAddress((void**)&qh,  g_qh);
    cudaGetSymbolAddress((void**)&ql,  g_ql);
    cudaGetSymbolAddress((void**)&kh,  g_kh);
    cudaGetSymbolAddress((void**)&kl,  g_kl);
    cudaGetSymbolAddress((void**)&vh,  g_vh);
    cudaGetSymbolAddress((void**)&vl,  g_vl);
    cudaGetSymbolAddress((void**)&ph,  g_ph);
    cudaGetSymbolAddress((void**)&pl,  g_pl);
    cudaGetSymbolAddress((void**)&aoh, g_aoh);
    cudaGetSymbolAddress((void**)&aol, g_aol);

    cudaFuncSetAttribute(mma_gemm_qkv,
                         cudaFuncAttributeMaxDynamicSharedMemorySize, GEMM_SMEM);
    cudaFuncSetAttribute(mma_gemm_out,
                         cudaFuncAttributeMaxDynamicSharedMemorySize, GEMM_SMEM);
    cudaFuncSetAttribute(attn_scores_mma,
                         cudaFuncAttributeMaxDynamicSharedMemorySize, SC2_SMEM);
    cudaFuncSetAttribute(attn_pv_mma,
                         cudaFuncAttributeMaxDynamicSharedMemorySize, PV_SMEM);

    // 0. pre-split inputs
    split_kernel<<<(MROWS * DD / 4 + 255) / 256, 256>>>(x, xh, xl, MROWS * DD / 4);
    split_kernel<<<(DD * 3 * DD / 4 + 255) / 256, 256>>>(w_in, wih, wil, DD * 3 * DD / 4);
    split_kernel<<<(DD * DD / 4 + 255) / 256, 256>>>(w_out, woh, wol, DD * DD / 4);

    // 1. QKV GEMM -> split q/k/v per head
    mma_gemm_qkv<<<dim3(3 * DD / 128, MROWS / 128), 256, GEMM_SMEM>>>(
        xh, xl, wih, wil, b_in, qh, ql, kh, kl, vh, vl, MROWS, 3 * DD, DD);

    // 2. scores + softmax (MMA) -> split P
    attn_scores_mma<<<dim3(SS / 32, HH, BB), 256, SC2_SMEM>>>(qh, ql, kh, kl, ph, pl);

    // 3. P @ V (MMA) -> split AO
    attn_pv_mma<<<dim3(SS / 128, HH, BB), 256, PV_SMEM>>>(ph, pl, vh, vl, aoh, aol);

    // 4. head-mean
    attn_mean_kernel<<<(BB * SS * SS / 8) / 256, 256>>>(ph, pl, out + (size_t)BB * SS * SS);

    // 5. output projection
    mma_gemm_out<<<dim3(DD / 128, MROWS / 128), 256, GEMM_SMEM>>>(
        aoh, aol, woh, wol, b_out, out, MROWS, DD, DD);
}